// round 2
// baseline (speedup 1.0000x reference)
#include <cuda_runtime.h>
#include <math.h>

// Problem dims
#define TSTEPS 63
#define BATCH  32
#define SEQ    64
#define HID    1024
#define EMB    512
#define VOC    32000
#define GATES  4096
#define HC     2048
#define MROWS  (TSTEPS*BATCH)   // 2016

// ---------------- scratch (static device globals; no runtime alloc) -------------
__device__ float g_Emb [MROWS*EMB];          //  4 MB  gathered embeddings, row r = t*32+b
__device__ float g_XP  [MROWS*GATES];        // 33 MB  x@W_ih^T + (b_ih+b_hh)
__device__ float g_h   [BATCH*HID];
__device__ float g_c   [BATCH*HID];
__device__ float g_hcat[BATCH*HC];           // [h | context]
__device__ float g_gpart[4][BATCH*GATES];    //  2 MB  split-K partials of h@W_hh^T
__device__ float g_dpart[8][MROWS*HID];      // 66 MB  split-K partials of hcat@W_w^T (per t)
__device__ float g_Dec [MROWS*HID];          //  8 MB  tanh(dec_raw + b_w)

// ---------------- init: copy h0/c0 -------------------------------------------
__global__ void k_init(const float* __restrict__ h0, const float* __restrict__ c0){
    int i = blockIdx.x*blockDim.x + threadIdx.x;
    if (i < BATCH*HID){ g_h[i] = h0[i]; g_c[i] = c0[i]; }
}

// ---------------- embedding gather -------------------------------------------
__global__ void k_embed(const int* __restrict__ tgt, const float* __restrict__ emb){
    int r = blockIdx.x;              // 0..2015
    int t = r >> 5, b = r & 31;
    int tok = tgt[b*64 + t];         // tgt is (B=32, T=64) row-major; use cols [0, T-1)
    const float4* src = (const float4*)(emb + (size_t)tok*EMB);
    float4*       dst = (float4*)(g_Emb + (size_t)r*EMB);
    dst[threadIdx.x] = src[threadIdx.x];   // 128 threads x float4 = 512 floats
}

// ---------------- XP = Emb @ W_ih^T + b_ih + b_hh  (2016 x 4096, K=512) ------
// 64x64 tile, BK=16, 256 thr, 4x4 per thread
__global__ void k_xp(const float* __restrict__ B,
                     const float* __restrict__ bih, const float* __restrict__ bhh){
    const int M = MROWS, N = GATES, K = EMB;
    __shared__ float sA[16][68];
    __shared__ float sB[16][68];
    int bm = blockIdx.y*64, bn = blockIdx.x*64;
    int tid = threadIdx.x;
    int tm = (tid>>4)<<2, tn = (tid&15)<<2;
    int lm = tid>>2, lk = (tid&3)<<2;
    float acc[4][4];
    #pragma unroll
    for(int i=0;i<4;i++){ acc[i][0]=0.f; acc[i][1]=0.f; acc[i][2]=0.f; acc[i][3]=0.f; }
    for (int k0=0;k0<K;k0+=16){
        int gm = bm+lm;
        float4 av = (gm < M) ? *(const float4*)(g_Emb + (size_t)gm*K + k0 + lk)
                             : make_float4(0.f,0.f,0.f,0.f);
        sA[lk+0][lm]=av.x; sA[lk+1][lm]=av.y; sA[lk+2][lm]=av.z; sA[lk+3][lm]=av.w;
        float4 bv = *(const float4*)(B + (size_t)(bn+lm)*K + k0 + lk);
        sB[lk+0][lm]=bv.x; sB[lk+1][lm]=bv.y; sB[lk+2][lm]=bv.z; sB[lk+3][lm]=bv.w;
        __syncthreads();
        #pragma unroll
        for(int kk=0;kk<16;kk++){
            float4 a = *(const float4*)&sA[kk][tm];
            float4 b = *(const float4*)&sB[kk][tn];
            float aa[4]={a.x,a.y,a.z,a.w}, bb[4]={b.x,b.y,b.z,b.w};
            #pragma unroll
            for(int i=0;i<4;i++)
                #pragma unroll
                for(int j=0;j<4;j++) acc[i][j] += aa[i]*bb[j];
        }
        __syncthreads();
    }
    #pragma unroll
    for(int i=0;i<4;i++){
        int m = bm+tm+i;
        if (m < M){
            #pragma unroll
            for(int j=0;j<4;j++){
                int n = bn+tn+j;
                g_XP[(size_t)m*N + n] = acc[i][j] + bih[n] + bhh[n];
            }
        }
    }
}

// ---------------- gates partial: g_gpart[slice] = h @ W_hh^T (K-slice) -------
// M=32, N=4096, K=1024 split into 4 slices of 256. 32x64 tile, 128 thr.
__global__ void k_gates(const float* __restrict__ B){
    const int N = GATES, K = HID;
    __shared__ float sA[16][36];
    __shared__ float sB[16][68];
    int bn = blockIdx.x*64;
    int Koff = blockIdx.y*256;
    int tid = threadIdx.x;               // 128
    int tm = (tid>>4)<<2, tn = (tid&15)<<2;
    int lm = tid>>2, lk = (tid&3)<<2;    // lm 0..31
    float acc[4][4];
    #pragma unroll
    for(int i=0;i<4;i++){ acc[i][0]=0.f; acc[i][1]=0.f; acc[i][2]=0.f; acc[i][3]=0.f; }
    for (int k0=0;k0<256;k0+=16){
        float4 av = *(const float4*)(g_h + (size_t)lm*K + Koff + k0 + lk);
        sA[lk+0][lm]=av.x; sA[lk+1][lm]=av.y; sA[lk+2][lm]=av.z; sA[lk+3][lm]=av.w;
        #pragma unroll
        for (int r=0;r<2;r++){
            int n = lm + 32*r;
            float4 bv = *(const float4*)(B + (size_t)(bn+n)*K + Koff + k0 + lk);
            sB[lk+0][n]=bv.x; sB[lk+1][n]=bv.y; sB[lk+2][n]=bv.z; sB[lk+3][n]=bv.w;
        }
        __syncthreads();
        #pragma unroll
        for(int kk=0;kk<16;kk++){
            float4 a = *(const float4*)&sA[kk][tm];
            float4 b = *(const float4*)&sB[kk][tn];
            float aa[4]={a.x,a.y,a.z,a.w}, bb[4]={b.x,b.y,b.z,b.w};
            #pragma unroll
            for(int i=0;i<4;i++)
                #pragma unroll
                for(int j=0;j<4;j++) acc[i][j] += aa[i]*bb[j];
        }
        __syncthreads();
    }
    float* dst = g_gpart[blockIdx.y];
    #pragma unroll
    for(int i=0;i<4;i++)
        #pragma unroll
        for(int j=0;j<4;j++)
            dst[(size_t)(tm+i)*N + bn+tn+j] = acc[i][j];
}

// ---------------- LSTM cell: sums gate partials + XP, updates h,c ------------
__global__ void k_cell(int t){
    int idx = blockIdx.x*blockDim.x + threadIdx.x;   // 32768
    int b = idx >> 10, j = idx & 1023;
    size_t base = (size_t)b*GATES;
    const float* xp = g_XP + ((size_t)t*BATCH + b)*GATES;
    float gi = xp[j], gf = xp[1024+j], gg = xp[2048+j], go = xp[3072+j];
    #pragma unroll
    for(int s=0;s<4;s++){
        const float* gp = g_gpart[s] + base;
        gi += gp[j]; gf += gp[1024+j]; gg += gp[2048+j]; go += gp[3072+j];
    }
    float i_ = 1.f/(1.f+expf(-gi));
    float f_ = 1.f/(1.f+expf(-gf));
    float g_ = tanhf(gg);
    float o_ = 1.f/(1.f+expf(-go));
    float c  = f_*g_c[idx] + i_*g_;
    g_c[idx] = c;
    float h  = o_*tanhf(c);
    g_h[idx] = h;
    g_hcat[(size_t)b*HC + j] = h;
}

// ---------------- attention: scores->softmax->context, one block per batch ---
__global__ void k_attn(const float* __restrict__ enc){
    int b = blockIdx.x, tid = threadIdx.x;   // 256 threads
    __shared__ float sh[HID];
    __shared__ float ss[SEQ];
    for (int i=tid;i<HID;i+=256) sh[i] = g_h[(size_t)b*HID+i];
    __syncthreads();
    int warp = tid>>5, lane = tid&31;
    for (int s=warp; s<SEQ; s+=8){
        const float* e = enc + ((size_t)b*SEQ + s)*HID;
        float acc = 0.f;
        for (int k=lane;k<HID;k+=32) acc += sh[k]*e[k];
        #pragma unroll
        for(int o=16;o;o>>=1) acc += __shfl_xor_sync(0xffffffffu, acc, o);
        if (!lane) ss[s] = acc;
    }
    __syncthreads();
    if (tid == 0){
        float mx = -1e30f;
        for(int s=0;s<SEQ;s++) mx = fmaxf(mx, ss[s]);
        float sum = 0.f;
        for(int s=0;s<SEQ;s++){ float e = expf(ss[s]-mx); ss[s]=e; sum+=e; }
        float inv = 1.f/sum;
        for(int s=0;s<SEQ;s++) ss[s] *= inv;
    }
    __syncthreads();
    int j = tid<<2;
    float c0=0.f,c1=0.f,c2=0.f,c3=0.f;
    for(int s=0;s<SEQ;s++){
        float a = ss[s];
        float4 v = *(const float4*)(enc + ((size_t)b*SEQ+s)*HID + j);
        c0 += a*v.x; c1 += a*v.y; c2 += a*v.z; c3 += a*v.w;
    }
    *(float4*)(g_hcat + (size_t)b*HC + HID + j) = make_float4(c0,c1,c2,c3);
}

// ---------------- dec partial: g_dpart[slice][t] = hcat @ W_w^T (K-slice) ----
// M=32, N=1024, K=2048 split into 8 slices of 256.
__global__ void k_dec(const float* __restrict__ B, int t){
    const int N = HID, K = HC;
    __shared__ float sA[16][36];
    __shared__ float sB[16][68];
    int bn = blockIdx.x*64;
    int Koff = blockIdx.y*256;
    int tid = threadIdx.x;               // 128
    int tm = (tid>>4)<<2, tn = (tid&15)<<2;
    int lm = tid>>2, lk = (tid&3)<<2;
    float acc[4][4];
    #pragma unroll
    for(int i=0;i<4;i++){ acc[i][0]=0.f; acc[i][1]=0.f; acc[i][2]=0.f; acc[i][3]=0.f; }
    for (int k0=0;k0<256;k0+=16){
        float4 av = *(const float4*)(g_hcat + (size_t)lm*K + Koff + k0 + lk);
        sA[lk+0][lm]=av.x; sA[lk+1][lm]=av.y; sA[lk+2][lm]=av.z; sA[lk+3][lm]=av.w;
        #pragma unroll
        for (int r=0;r<2;r++){
            int n = lm + 32*r;
            float4 bv = *(const float4*)(B + (size_t)(bn+n)*K + Koff + k0 + lk);
            sB[lk+0][n]=bv.x; sB[lk+1][n]=bv.y; sB[lk+2][n]=bv.z; sB[lk+3][n]=bv.w;
        }
        __syncthreads();
        #pragma unroll
        for(int kk=0;kk<16;kk++){
            float4 a = *(const float4*)&sA[kk][tm];
            float4 b = *(const float4*)&sB[kk][tn];
            float aa[4]={a.x,a.y,a.z,a.w}, bb[4]={b.x,b.y,b.z,b.w};
            #pragma unroll
            for(int i=0;i<4;i++)
                #pragma unroll
                for(int j=0;j<4;j++) acc[i][j] += aa[i]*bb[j];
        }
        __syncthreads();
    }
    float* dst = g_dpart[blockIdx.y] + (size_t)t*BATCH*HID;
    #pragma unroll
    for(int i=0;i<4;i++)
        #pragma unroll
        for(int j=0;j<4;j++)
            dst[(size_t)(tm+i)*N + bn+tn+j] = acc[i][j];
}

// ---------------- tanh reduce over the 8 dec slices --------------------------
__global__ void k_tanh(const float* __restrict__ bw){
    int idx = blockIdx.x*blockDim.x + threadIdx.x;   // 2016*1024
    float s = bw[idx & 1023];
    #pragma unroll
    for(int p=0;p<8;p++) s += g_dpart[p][idx];
    g_Dec[idx] = tanhf(s);
}

// ---------------- output GEMM: Dec(2016x1024) @ W_out^T(1024x32000) ----------
// 128x128 tile, BK=16, 256 thr, 8x8 per thread; scatter rows (t,b)->(b,t).
__global__ void k_out(const float* __restrict__ B,
                      const float* __restrict__ bout, float* __restrict__ out){
    const int M = MROWS, N = VOC, K = HID;
    __shared__ float sA[16][132];
    __shared__ float sB[16][132];
    int bm = blockIdx.y*128, bn = blockIdx.x*128;
    int tid = threadIdx.x;                    // 256
    int tm = (tid>>4)<<3, tn = (tid&15)<<3;
    int lm = tid>>1, lk = (tid&1)<<3;         // lm 0..127, lk 0 or 8
    float acc[8][8];
    #pragma unroll
    for(int i=0;i<8;i++)
        #pragma unroll
        for(int j=0;j<8;j++) acc[i][j]=0.f;
    for (int k0=0;k0<K;k0+=16){
        int gm = bm+lm;
        #pragma unroll
        for(int h=0;h<2;h++){
            int kk = lk + 4*h;
            float4 av = (gm < M) ? *(const float4*)(g_Dec + (size_t)gm*K + k0 + kk)
                                 : make_float4(0.f,0.f,0.f,0.f);
            sA[kk+0][lm]=av.x; sA[kk+1][lm]=av.y; sA[kk+2][lm]=av.z; sA[kk+3][lm]=av.w;
            float4 bv = *(const float4*)(B + (size_t)(bn+lm)*K + k0 + kk);
            sB[kk+0][lm]=bv.x; sB[kk+1][lm]=bv.y; sB[kk+2][lm]=bv.z; sB[kk+3][lm]=bv.w;
        }
        __syncthreads();
        #pragma unroll
        for(int kk=0;kk<16;kk++){
            float4 a0 = *(const float4*)&sA[kk][tm];
            float4 a1 = *(const float4*)&sA[kk][tm+4];
            float4 b0 = *(const float4*)&sB[kk][tn];
            float4 b1 = *(const float4*)&sB[kk][tn+4];
            float aa[8]={a0.x,a0.y,a0.z,a0.w,a1.x,a1.y,a1.z,a1.w};
            float bb[8]={b0.x,b0.y,b0.z,b0.w,b1.x,b1.y,b1.z,b1.w};
            #pragma unroll
            for(int i=0;i<8;i++)
                #pragma unroll
                for(int j=0;j<8;j++) acc[i][j] += aa[i]*bb[j];
        }
        __syncthreads();
    }
    #pragma unroll
    for(int i=0;i<8;i++){
        int m = bm+tm+i;
        if (m < M){
            int t = m >> 5, b = m & 31;
            float* p = out + (size_t)b*(TSTEPS*VOC) + (size_t)t*VOC + bn + tn;
            float4 v0, v1;
            int n = bn+tn;
            v0.x = acc[i][0]+bout[n+0]; v0.y = acc[i][1]+bout[n+1];
            v0.z = acc[i][2]+bout[n+2]; v0.w = acc[i][3]+bout[n+3];
            v1.x = acc[i][4]+bout[n+4]; v1.y = acc[i][5]+bout[n+5];
            v1.z = acc[i][6]+bout[n+6]; v1.w = acc[i][7]+bout[n+7];
            *(float4*)p       = v0;
            *(float4*)(p + 4) = v1;
        }
    }
}

// ---------------- launch ------------------------------------------------------
extern "C" void kernel_launch(void* const* d_in, const int* in_sizes, int n_in,
                              void* d_out, int out_size){
    const int*   tgt  = (const int*)  d_in[0];
    const float* h0   = (const float*)d_in[1];
    const float* c0   = (const float*)d_in[2];
    const float* enc  = (const float*)d_in[3];
    const float* emb  = (const float*)d_in[4];
    const float* Wih  = (const float*)d_in[5];
    const float* Whh  = (const float*)d_in[6];
    const float* bih  = (const float*)d_in[7];
    const float* bhh  = (const float*)d_in[8];
    const float* Ww   = (const float*)d_in[9];
    const float* bw   = (const float*)d_in[10];
    const float* Wout = (const float*)d_in[11];
    const float* bout = (const float*)d_in[12];
    float* out = (float*)d_out;

    k_init <<<128, 256>>>(h0, c0);
    k_embed<<<MROWS, 128>>>(tgt, emb);
    k_xp   <<<dim3(GATES/64, (MROWS+63)/64), 256>>>(Wih, bih, bhh);

    for (int t = 0; t < TSTEPS; t++){
        k_gates<<<dim3(GATES/64, 4), 128>>>(Whh);
        k_cell <<<128, 256>>>(t);
        k_attn <<<BATCH, 256>>>(enc);
        k_dec  <<<dim3(HID/64, 8), 128>>>(Ww, t);
    }

    k_tanh<<<(MROWS*HID)/256, 256>>>(bw);
    k_out <<<dim3(VOC/128, (MROWS+127)/128), 256>>>(Wout, bout, out);
}